// round 1
// baseline (speedup 1.0000x reference)
#include <cuda_runtime.h>
#include <math.h>
#include <float.h>

#define NOFF 20
#define HDIM 128
#define SEQN 8192
#define NH   16
#define NB   2
#define WARPS 8
#define QPW   8   // queries per warp per block

__constant__ int c_offs[NOFF] = {1,2,3,4,5,6,7,8,9,11,13,15,16,23,32,64,128,256,512,1024};

// ---- packed f32x2 helpers (sm_100+; ptxas never auto-fuses these) ----
__device__ __forceinline__ unsigned long long f2add(unsigned long long a, unsigned long long b) {
    unsigned long long d;
    asm("add.rn.f32x2 %0, %1, %2;" : "=l"(d) : "l"(a), "l"(b));
    return d;
}
__device__ __forceinline__ unsigned long long f2fma(unsigned long long a, unsigned long long b, unsigned long long c) {
    unsigned long long d;
    asm("fma.rn.f32x2 %0, %1, %2, %3;" : "=l"(d) : "l"(a), "l"(b), "l"(c));
    return d;
}
__device__ __forceinline__ float2 f2unpack(unsigned long long a) {
    float lo, hi;
    asm("mov.b64 {%0, %1}, %2;" : "=f"(lo), "=f"(hi) : "l"(a));
    return make_float2(lo, hi);
}
__device__ __forceinline__ unsigned long long f2bcast(float x) {
    unsigned long long d;
    asm("mov.b64 %0, {%1, %1};" : "=l"(d) : "f"(x));
    return d;
}

__global__ void __launch_bounds__(256) dsqg_fwd(
    const float* __restrict__ q, const float* __restrict__ k, const float* __restrict__ v,
    const float* __restrict__ pb, const float* __restrict__ se, float* __restrict__ out)
{
    constexpr int offs[NOFF] = {1,2,3,4,5,6,7,8,9,11,13,15,16,23,32,64,128,256,512,1024};

    __shared__ float se_s[NOFF * HDIM];       // scale_embed, fused into k
    __shared__ float pb_s[NOFF];              // pos_bias column for this head
    __shared__ float red_s[WARPS][32][21];    // stride-21 pad: conflict-free transpose reduce
    __shared__ float p_s[WARPS][NOFF];        // softmax weights broadcast

    const int tid = threadIdx.x;
    const int w   = tid >> 5;
    const int l   = tid & 31;

    const int bid = blockIdx.x;
    const int bh  = bid >> 7;                       // 128 blocks per (b,h)
    const int n0  = (bid & 127) * (WARPS * QPW);    // 64 queries per block
    const int h   = bh & (NH - 1);

    // stage scale_embed (20x128 f32) and pos_bias column
    for (int i = tid; i < NOFF * HDIM / 4; i += 256)
        ((float4*)se_s)[i] = ((const float4*)se)[i];
    if (tid < NOFF) pb_s[tid] = pb[tid * NH + h];
    __syncthreads();

    const float sc = 0.088388347648318447f;   // 1/sqrt(128)
    const size_t base = (size_t)bh * SEQN * HDIM;
    const float* kb = k + base;
    const float* vb = v + base;
    const int d4 = l * 4;

    for (int it = 0; it < QPW; ++it) {
        const int n = n0 + it * WARPS + w;    // warps interleaved: adjacent n active together
        const ulonglong2 qq = *(const ulonglong2*)(q + base + (size_t)n * HDIM + d4);

        unsigned long long acc[NOFF];
#pragma unroll
        for (int j = 0; j < NOFF; ++j) acc[j] = 0ULL;

        // ---- score dots: q . (k[n-dj] + se_j), packed f32x2 ----
#pragma unroll
        for (int j = 0; j < NOFF; ++j) {
            int kp  = n - offs[j];
            int kpc = kp < 0 ? 0 : kp;
            const ulonglong2 kk = *(const ulonglong2*)(kb + (size_t)kpc * HDIM + d4);
            const ulonglong2 sj = *(const ulonglong2*)(se_s + j * HDIM + d4);
            acc[j] = f2fma(qq.x, f2add(kk.x, sj.x), acc[j]);
            acc[j] = f2fma(qq.y, f2add(kk.y, sj.y), acc[j]);
        }

        // ---- warp reduce via smem transpose ----
#pragma unroll
        for (int j = 0; j < NOFF; ++j) {
            float2 t = f2unpack(acc[j]);
            red_s[w][l][j] = t.x + t.y;
        }
        __syncwarp();

        float s = -FLT_MAX;
        bool valid = false;
        if (l < NOFF) {
            float t = 0.f;
#pragma unroll
            for (int i = 0; i < 32; ++i) t += red_s[w][i][l];
            int kp = n - c_offs[l];
            valid = (kp >= 0);
            if (valid) s = t * sc + pb_s[l];
        }

        // ---- lane-distributed softmax over the 20 offsets ----
        float m = s;
#pragma unroll
        for (int o = 16; o; o >>= 1) m = fmaxf(m, __shfl_xor_sync(0xffffffffu, m, o));
        float e = valid ? __expf(s - m) : 0.f;
        float lsum = e;
#pragma unroll
        for (int o = 16; o; o >>= 1) lsum += __shfl_xor_sync(0xffffffffu, lsum, o);
        float pval = e * (lsum > 0.f ? 1.f / lsum : 0.f);  // all-invalid row (n=0) -> p=0 -> out=0
        if (l < NOFF) p_s[w][l] = pval;
        __syncwarp();

        // ---- output: sum_j p_j * v[n-dj], packed f32x2 ----
        unsigned long long o01 = 0ULL, o23 = 0ULL;
#pragma unroll
        for (int j = 0; j < NOFF; ++j) {
            int kp  = n - offs[j];
            int kpc = kp < 0 ? 0 : kp;
            const ulonglong2 vv = *(const ulonglong2*)(vb + (size_t)kpc * HDIM + d4);
            unsigned long long pp = f2bcast(p_s[w][j]);
            o01 = f2fma(pp, vv.x, o01);
            o23 = f2fma(pp, vv.y, o23);
        }
        float2 a = f2unpack(o01), b2 = f2unpack(o23);
        *(float4*)(out + base + (size_t)n * HDIM + d4) = make_float4(a.x, a.y, b2.x, b2.y);
        __syncwarp();   // protect red_s/p_s reuse across iterations
    }
}

extern "C" void kernel_launch(void* const* d_in, const int* in_sizes, int n_in,
                              void* d_out, int out_size) {
    const float* q  = (const float*)d_in[0];
    const float* k  = (const float*)d_in[1];
    const float* v  = (const float*)d_in[2];
    const float* pb = (const float*)d_in[3];
    const float* se = (const float*)d_in[4];
    (void)in_sizes; (void)n_in; (void)out_size;
    dsqg_fwd<<<NB * NH * (SEQN / (WARPS * QPW)), 256>>>(q, k, v, pb, se, (float*)d_out);
}